// round 16
// baseline (speedup 1.0000x reference)
#include <cuda_runtime.h>
#include <cuda_fp16.h>
#include <cstdint>
#include <math.h>

#define HID 128
#define NEAR_T 0.01f
#define FAR_T 10.0f
#define MAX_IT 32
#define NTHREADS 512
#define ASTRIDE 68
#define AWORK 2176          // words per group A buffer (32*68)

// ---- smem layout (float-word offsets) ----
#define OFF_BPK   0        // 16384 : B frags float4 (b0h,b1h,b0l,b1l)
#define OFF_AH    16384    // 17408 : Ah, 4 workers x 2 groups x 2176
#define OFF_AL    33792    // 17408 : Al (unscaled residual)
#define OFF_W1P   51200    // 544 : W1 interleaved, 4 kseg blocks
#define OFF_WC1B  51744    // 512
#define OFF_WC2B  52256    // 512
#define OFF_BW    52768    // 256 : (b2[n], W3[n])
#define OFF_BC2   53024    // 4
#define OFF_SCR   53028    // 1024 : 4 workers x 256 (part0@0, part1@64, cp@128, ints@224)
#define SMEM_WORDS 54064   // 216256 bytes -> 1 CTA/SM

__device__ int g_tile_ctr;
__global__ void reset_ctr_kernel() { g_tile_ctr = 0; }

#define BAR_P() asm volatile("bar.sync %0, 128;" :: "r"(1 + worker) : "memory")
#define BAR_M() asm volatile("bar.sync %0, 64;"  :: "r"(5 + worker) : "memory")

__device__ __forceinline__ uint32_t h2u(__half2 h) {
    return *reinterpret_cast<uint32_t*>(&h);
}
__device__ __forceinline__ uint32_t smem_u32(const void* p) {
    uint32_t a;
    asm("{ .reg .u64 t; cvta.to.shared.u64 t, %1; cvt.u32.u64 %0, t; }" : "=r"(a) : "l"(p));
    return a;
}
__device__ __forceinline__ void mma16(float* c, const uint32_t* a,
                                      uint32_t b0, uint32_t b1) {
    asm volatile(
        "mma.sync.aligned.m16n8k16.row.col.f32.f16.f16.f32 "
        "{%0,%1,%2,%3}, {%4,%5,%6,%7}, {%8,%9}, {%0,%1,%2,%3};"
        : "+f"(c[0]), "+f"(c[1]), "+f"(c[2]), "+f"(c[3])
        : "r"(a[0]), "r"(a[1]), "r"(a[2]), "r"(a[3]), "r"(b0), "r"(b1));
}
__device__ __forceinline__ void ldsm4(uint32_t* r, uint32_t addr) {
    asm volatile("ldmatrix.sync.aligned.m8n8.x4.shared.b16 {%0,%1,%2,%3}, [%4];"
        : "=r"(r[0]), "=r"(r[1]), "=r"(r[2]), "=r"(r[3]) : "r"(addr));
}

// layer 1 for one ray (lane), 64 k (2 ksegs selected by kh), fp16 hi + unscaled lo
__device__ __forceinline__ void compute_h1(const float4* w1p, uint32_t* AhW, uint32_t* AlW,
                                           int ray, int kh,
                                           float px, float py, float pz)
{
    #pragma unroll
    for (int seg = 0; seg < 2; ++seg) {
        const float4* blk = w1p + (2 * kh + seg) * 34;
        #pragma unroll
        for (int j = 0; j < 4; ++j) {
            uint32_t hw[4], lw[4];
            #pragma unroll
            for (int q = 0; q < 4; ++q) {
                int kpl = j * 4 + q;
                float4 q0 = blk[kpl * 2], q1 = blk[kpl * 2 + 1];
                float h0 = fmaxf(fmaf(px, q0.x, fmaf(py, q0.y, fmaf(pz, q0.z, q0.w))), 0.f);
                float h1v = fmaxf(fmaf(px, q1.x, fmaf(py, q1.y, fmaf(pz, q1.z, q1.w))), 0.f);
                __half2 hh = __floats2half2_rn(h0, h1v);
                float2 bk = __half22float2(hh);
                __half2 ll = __floats2half2_rn(h0 - bk.x, h1v - bk.y);
                hw[q] = h2u(hh);
                lw[q] = h2u(ll);
            }
            int base = ray * ASTRIDE + (2 * kh + seg) * 16 + j * 4;
            *(uint4*)(AhW + base) = make_uint4(hw[0], hw[1], hw[2], hw[3]);
            *(uint4*)(AlW + base) = make_uint4(lw[0], lw[1], lw[2], lw[3]);
        }
    }
}

// phase B for one group: M32 x N64 (this warp's ng half), 3-term fp16, fused layer 3
__device__ __forceinline__ void do_B(const float4* bbase, uint32_t ahA, uint32_t alA,
                                     const float* bw, float* part,
                                     int ng, int gid, int tig)
{
    float c[2][8][4];
    #pragma unroll
    for (int mh = 0; mh < 2; ++mh)
        #pragma unroll
        for (int j = 0; j < 8; ++j)
            #pragma unroll
            for (int q = 0; q < 4; ++q) c[mh][j][q] = 0.f;

    #pragma unroll
    for (int ks = 0; ks < 8; ++ks) {
        uint32_t ah[2][4], al[2][4];
        ldsm4(ah[0], ahA + ks * 32);
        ldsm4(ah[1], ahA + 4352 + ks * 32);
        ldsm4(al[0], alA + ks * 32);
        ldsm4(al[1], alA + 4352 + ks * 32);
        #pragma unroll
        for (int j = 0; j < 8; ++j) {
            float4 bv = bbase[ks * 512 + j * 32];
            uint32_t b0h = __float_as_uint(bv.x), b1h = __float_as_uint(bv.y);
            uint32_t b0l = __float_as_uint(bv.z), b1l = __float_as_uint(bv.w);
            mma16(c[0][j], ah[0], b0h, b1h);
            mma16(c[1][j], ah[1], b0h, b1h);
            mma16(c[0][j], al[0], b0h, b1h);
            mma16(c[1][j], al[1], b0h, b1h);
            mma16(c[0][j], ah[0], b0l, b1l);
            mma16(c[1][j], ah[1], b0l, b1l);
        }
    }

    float rs[2][2] = {{0.f, 0.f}, {0.f, 0.f}};
    #pragma unroll
    for (int mh = 0; mh < 2; ++mh) {
        #pragma unroll
        for (int j = 0; j < 8; ++j) {
            const int n0 = ng * 64 + j * 8 + tig * 2;
            float4 bwv = *(const float4*)(bw + n0 * 2);
            float f0 = c[mh][j][0] + bwv.x;
            float f1 = c[mh][j][1] + bwv.z;
            float f2 = c[mh][j][2] + bwv.x;
            float f3 = c[mh][j][3] + bwv.z;
            rs[mh][0] = fmaf(fmaxf(f0, 0.f), bwv.y, rs[mh][0]);
            rs[mh][0] = fmaf(fmaxf(f1, 0.f), bwv.w, rs[mh][0]);
            rs[mh][1] = fmaf(fmaxf(f2, 0.f), bwv.y, rs[mh][1]);
            rs[mh][1] = fmaf(fmaxf(f3, 0.f), bwv.w, rs[mh][1]);
        }
    }
    #pragma unroll
    for (int off = 1; off < 4; off <<= 1) {
        rs[0][0] += __shfl_xor_sync(0xffffffffu, rs[0][0], off);
        rs[0][1] += __shfl_xor_sync(0xffffffffu, rs[0][1], off);
        rs[1][0] += __shfl_xor_sync(0xffffffffu, rs[1][0], off);
        rs[1][1] += __shfl_xor_sync(0xffffffffu, rs[1][1], off);
    }
    if (tig == 0) {
        part[(gid)      * 2 + ng] = rs[0][0];
        part[(gid + 8)  * 2 + ng] = rs[0][1];
        part[(gid + 16) * 2 + ng] = rs[1][0];
        part[(gid + 24) * 2 + ng] = rs[1][1];
    }
}

extern __shared__ float smem[];

__global__ void __launch_bounds__(NTHREADS, 1)
sphere_trace_kernel(const float* __restrict__ org,
                    const float* __restrict__ dir,
                    const float* __restrict__ W1, const float* __restrict__ b1,
                    const float* __restrict__ W2, const float* __restrict__ b2,
                    const float* __restrict__ W3, const float* __restrict__ b3,
                    const float* __restrict__ Wc1, const float* __restrict__ bc1,
                    const float* __restrict__ Wc2, const float* __restrict__ bc2,
                    float* __restrict__ out, int N)
{
    float4* Bpk = (float4*)(smem + OFF_BPK);
    float*  bw  = smem + OFF_BW;

    const uint32_t sb = smem_u32(smem);
    const int t      = threadIdx.x;
    const int lane   = t & 31;
    const int wid    = t >> 5;
    const int worker = wid & 3;         // worker's 4 warps share one SMSP
    const int role   = wid >> 2;        // 0,1 = MMA (ng=role); 2,3 = march (kh=role-2)
    const int gid    = lane >> 2;
    const int tig    = lane & 3;

    float* scrW = smem + OFF_SCR + worker * 256;
    int*   iscr = (int*)scrW;           // [224]=base0 [225]=base1 [226]=act0 [227]=act1
    float* cp   = scrW + 128;

    uint32_t* AhW0 = (uint32_t*)(smem + OFF_AH) + (worker * 2 + 0) * AWORK;
    uint32_t* AlW0 = (uint32_t*)(smem + OFF_AL) + (worker * 2 + 0) * AWORK;
    uint32_t* AhW1 = AhW0 + AWORK;
    uint32_t* AlW1 = AlW0 + AWORK;

    // ---- one-time staging (whole CTA) ----
    for (int idx = t; idx < 4096; idx += NTHREADS) {
        int ln = idx & 31, jn = (idx >> 5) & 15, ks = idx >> 9;
        int n  = jn * 8 + (ln >> 2);
        int k0 = ks * 16 + 2 * (ln & 3);
        float w00 = W2[k0*HID + n],     w01 = W2[(k0+1)*HID + n];
        float w10 = W2[(k0+8)*HID + n], w11 = W2[(k0+9)*HID + n];
        __half2 bh0 = __floats2half2_rn(w00, w01);
        __half2 bh1 = __floats2half2_rn(w10, w11);
        float2 r0 = __half22float2(bh0), r1 = __half22float2(bh1);
        __half2 bl0 = __floats2half2_rn(w00 - r0.x, w01 - r0.y);
        __half2 bl1 = __floats2half2_rn(w10 - r1.x, w11 - r1.y);
        Bpk[idx] = make_float4(__uint_as_float(h2u(bh0)), __uint_as_float(h2u(bh1)),
                               __uint_as_float(h2u(bl0)), __uint_as_float(h2u(bl1)));
    }
    if (t < 128) {
        int kseg = t >> 5, klocal = t & 31, kpl = klocal >> 1, hh = klocal & 1;
        ((float4*)(smem + OFF_W1P))[kseg * 34 + kpl * 2 + hh] =
            make_float4(W1[t], W1[HID + t], W1[2*HID + t], b1[t]);
        float* wc1b = smem + OFF_WC1B;
        float* wc2b = smem + OFF_WC2B;
        wc1b[t*4+0] = Wc1[t];       wc1b[t*4+1] = Wc1[HID+t];
        wc1b[t*4+2] = Wc1[2*HID+t]; wc1b[t*4+3] = bc1[t];
        wc2b[t*4+0] = Wc2[3*t];     wc2b[t*4+1] = Wc2[3*t+1];
        wc2b[t*4+2] = Wc2[3*t+2];   wc2b[t*4+3] = 0.0f;
        bw[2*t]   = b2[t];
        bw[2*t+1] = W3[t];
    }
    if (t < 4) (smem + OFF_BC2)[t] = (t < 3) ? bc2[t] : 0.0f;
    const float bias3 = b3[0];

    // initial ray grabs (one thread per worker)
    if (role == 2 && lane == 0) {
        int b0 = atomicAdd(&g_tile_ctr, 32);
        int b1i = atomicAdd(&g_tile_ctr, 32);
        iscr[224] = b0; iscr[225] = b1i;
        iscr[226] = (b0 < N) ? 1 : 0;
        iscr[227] = (b1i < N) ? 1 : 0;
    }
    __syncthreads();

    const float4* w1p = (const float4*)(smem + OFF_W1P);
    const float*  bc  = smem + OFF_BC2;

    // MMA addressing
    const uint32_t laneoff = (uint32_t)(lane & 15) * 272 + (uint32_t)((lane >> 4) & 1) * 16;
    const uint32_t ahA0 = sb + (OFF_AH + (worker*2+0) * AWORK) * 4 + laneoff;
    const uint32_t alA0 = sb + (OFF_AL + (worker*2+0) * AWORK) * 4 + laneoff;
    const uint32_t ahA1 = ahA0 + AWORK * 4;
    const uint32_t alA1 = alA0 + AWORK * 4;
    const int ng = role;                           // valid for roles 0,1
    const float4* bbase = Bpk + (role & 1) * 256 + lane;

    // march state (two groups, mirrored in both march warps)
    const int kh = role - 2;                       // valid for roles 2,3
    float px0=0,py0=0,pz0=0,dx0=0,dy0=0,dz0=0,dist0=0;
    float px1=0,py1=0,pz1=0,dx1=0,dy1=0,dz1=0,dist1=0;
    int ray0=0, ray1=0, it0=0, it1=0;
    bool hit0=false, hit1=false, frz0=true, frz1=true, vr0=false, vr1=false;
    bool bready0=false, bready1=false;

    if (role >= 2) {
        int b0 = iscr[224], b1i = iscr[225];
        if (iscr[226]) {
            ray0 = b0 + lane; vr0 = ray0 < N; if (!vr0) ray0 = N - 1;
            px0 = org[3*ray0]; py0 = org[3*ray0+1]; pz0 = org[3*ray0+2];
            dx0 = dir[3*ray0]; dy0 = dir[3*ray0+1]; dz0 = dir[3*ray0+2];
            frz0 = !vr0;
            compute_h1(w1p, AhW0, AlW0, lane, kh, px0, py0, pz0);
        }
        if (iscr[227]) {
            ray1 = b1i + lane; vr1 = ray1 < N; if (!vr1) ray1 = N - 1;
            px1 = org[3*ray1]; py1 = org[3*ray1+1]; pz1 = org[3*ray1+2];
            dx1 = dir[3*ray1]; dy1 = dir[3*ray1+1]; dz1 = dir[3*ray1+2];
            frz1 = !vr1;
            compute_h1(w1p, AhW1, AlW1, lane, kh, px1, py1, pz1);
        }
    }

// march + (group-level) refill for group G — mirrored across both march warps
#define MARCH(G, AhWg, AlWg) do {                                              \
    if (!frz##G) {                                                             \
        float2 pp = *(const float2*)(scrW + (G)*64 + lane*2);                  \
        float sdf = bias3 + pp.x + pp.y;                                       \
        bool valid = (sdf <= NEAR_T) && (dist##G < FAR_T);                     \
        hit##G = hit##G || valid;                                              \
        if (valid) frz##G = true;                                              \
        else {                                                                 \
            dist##G += sdf;                                                    \
            px##G = fmaf(dx##G, sdf, px##G);                                   \
            py##G = fmaf(dy##G, sdf, py##G);                                   \
            pz##G = fmaf(dz##G, sdf, pz##G);                                   \
        }                                                                      \
    }                                                                          \
    it##G++;                                                                   \
    unsigned _bal = __ballot_sync(0xffffffffu, frz##G);                        \
    bool _allf = (_bal == 0xffffffffu) || (it##G >= MAX_IT);                   \
    if (!_allf) {                                                              \
        if (!frz##G) compute_h1(w1p, AhWg, AlWg, lane, kh, px##G, py##G, pz##G); \
    } else {                                                                   \
        float c0 = 0.f, c1 = 0.f, c2 = 0.f;                                    \
        {                                                                      \
            const float4* w1c = (const float4*)(smem + OFF_WC1B) + kh * 64;    \
            const float4* w2c = (const float4*)(smem + OFF_WC2B) + kh * 64;    \
            _Pragma("unroll 4")                                                \
            for (int j = 0; j < 64; ++j) {                                     \
                float4 q = w1c[j], wv = w2c[j];                                \
                float h = fmaxf(fmaf(px##G, q.x, fmaf(py##G, q.y,              \
                                fmaf(pz##G, q.z, q.w))), 0.f);                 \
                c0 = fmaf(h, wv.x, c0);                                        \
                c1 = fmaf(h, wv.y, c1);                                        \
                c2 = fmaf(h, wv.z, c2);                                        \
            }                                                                  \
        }                                                                      \
        if (kh == 1) {                                                         \
            cp[lane*3+0] = c0; cp[lane*3+1] = c1; cp[lane*3+2] = c2;           \
        }                                                                      \
        if (kh == 0 && lane == 0)                                              \
            iscr[224 + (G)] = atomicAdd(&g_tile_ctr, 32);                      \
        BAR_M();                                                               \
        if (kh == 0 && vr##G) {                                                \
            bool mask = hit##G || (dist##G < FAR_T);                           \
            float o0 = c0 + cp[lane*3+0] + bc[0];                              \
            float o1 = c1 + cp[lane*3+1] + bc[1];                              \
            float o2 = c2 + cp[lane*3+2] + bc[2];                              \
            out[3*ray##G]     = mask ? (1.0f / (1.0f + expf(-o0))) : 0.0f;     \
            out[3*ray##G + 1] = mask ? (1.0f / (1.0f + expf(-o1))) : 0.0f;     \
            out[3*ray##G + 2] = mask ? (1.0f / (1.0f + expf(-o2))) : 0.0f;     \
        }                                                                      \
        int _nb = iscr[224 + (G)];                                             \
        if (_nb < N) {                                                         \
            ray##G = _nb + lane; vr##G = ray##G < N;                           \
            if (!vr##G) ray##G = N - 1;                                        \
            px##G = org[3*ray##G]; py##G = org[3*ray##G+1]; pz##G = org[3*ray##G+2]; \
            dx##G = dir[3*ray##G]; dy##G = dir[3*ray##G+1]; dz##G = dir[3*ray##G+2]; \
            dist##G = 0.f; hit##G = false; frz##G = !vr##G; it##G = 0;         \
            compute_h1(w1p, AhWg, AlWg, lane, kh, px##G, py##G, pz##G);        \
        } else {                                                               \
            if (kh == 0 && lane == 0) iscr[226 + (G)] = 0;                     \
        }                                                                      \
    }                                                                          \
} while (0)

    // ---- phase loop (unrolled by 2 so group indices are compile-time) ----
    for (;;) {
        // phase s=0 : B(G0) || march(G1)
        BAR_P();
        {
            int a0 = iscr[226], a1 = iscr[227];
            if (!(a0 | a1)) break;
            if (role < 2) {
                if (a0) do_B(bbase, ahA0, alA0, bw, scrW, ng, gid, tig);
            } else {
                if (bready1) MARCH(1, AhW1, AlW1);
                bready0 = (a0 != 0);
            }
        }
        // phase s=1 : B(G1) || march(G0)
        BAR_P();
        {
            int a0 = iscr[226], a1 = iscr[227];
            if (!(a0 | a1)) break;
            if (role < 2) {
                if (a1) do_B(bbase, ahA1, alA1, bw, scrW + 64, ng, gid, tig);
            } else {
                if (bready0) MARCH(0, AhW0, AlW0);
                bready1 = (a1 != 0);
            }
        }
    }
}

extern "C" void kernel_launch(void* const* d_in, const int* in_sizes, int n_in,
                              void* d_out, int out_size)
{
    const float* org = (const float*)d_in[0];
    const float* dir = (const float*)d_in[1];
    const float* W1  = (const float*)d_in[2];
    const float* b1  = (const float*)d_in[3];
    const float* W2  = (const float*)d_in[4];
    const float* b2  = (const float*)d_in[5];
    const float* W3  = (const float*)d_in[6];
    const float* b3  = (const float*)d_in[7];
    const float* Wc1 = (const float*)d_in[8];
    const float* bc1 = (const float*)d_in[9];
    const float* Wc2 = (const float*)d_in[10];
    const float* bc2 = (const float*)d_in[11];
    float* out = (float*)d_out;

    const int N = in_sizes[0] / 3;
    const int smem_bytes = SMEM_WORDS * sizeof(float);

    cudaFuncSetAttribute(sphere_trace_kernel,
                         cudaFuncAttributeMaxDynamicSharedMemorySize, smem_bytes);

    reset_ctr_kernel<<<1, 1>>>();

    int nblocks = 152;     // 1 persistent CTA/SM: 4 workers (2 MMA + 2 march warps each)
    sphere_trace_kernel<<<nblocks, NTHREADS, smem_bytes>>>(
        org, dir, W1, b1, W2, b2, W3, b3, Wc1, bc1, Wc2, bc2, out, N);
}

// round 17
// speedup vs baseline: 1.2108x; 1.2108x over previous
#include <cuda_runtime.h>
#include <cuda_fp16.h>
#include <cstdint>
#include <math.h>

#define HID 128
#define NEAR_T 0.01f
#define FAR_T 10.0f
#define MAX_IT 32
#define NTHREADS 512
#define ASTRIDE 68
#define AWORK 2176          // words per worker A buffer (32*68)
#define RTHRESH 8           // pending lanes before a refill batch

// lane modes
#define M_MARCH 0
#define M_PEND  1
#define M_INACT 2

// ---- smem layout (float-word offsets) ----
#define OFF_BPK   0        // 16384 : B frags float4 (b0h,b1h,b0l,b1l)
#define OFF_AH    16384    // 17408 : Ah, 8 workers x 2176 words
#define OFF_AL    33792    // 17408 : Al (unscaled residual)
#define OFF_W1P   51200    // 544 : W1 interleaved, 4 kseg blocks
#define OFF_WC1B  51744    // 512
#define OFF_WC2B  52256    // 512
#define OFF_BW    52768    // 256 : (b2[n], W3[n])
#define OFF_BC2   53024    // 4
#define OFF_SCR   53028    // 2048 : 8 workers x 256 (part@0, color@64, asn@160)
#define OFF_TILE  55076    // 8 ints
#define SMEM_WORDS 55088   // 220352 bytes -> 1 CTA/SM

__device__ int g_tile_ctr;
__global__ void reset_ctr_kernel() { g_tile_ctr = 0; }

#define BAR_W(id) asm volatile("bar.sync %0, 64;" :: "r"(id) : "memory")

__device__ __forceinline__ uint32_t h2u(__half2 h) {
    return *reinterpret_cast<uint32_t*>(&h);
}
__device__ __forceinline__ uint32_t smem_u32(const void* p) {
    uint32_t a;
    asm("{ .reg .u64 t; cvta.to.shared.u64 t, %1; cvt.u32.u64 %0, t; }" : "=r"(a) : "l"(p));
    return a;
}
__device__ __forceinline__ void mma16(float* c, const uint32_t* a,
                                      uint32_t b0, uint32_t b1) {
    asm volatile(
        "mma.sync.aligned.m16n8k16.row.col.f32.f16.f16.f32 "
        "{%0,%1,%2,%3}, {%4,%5,%6,%7}, {%8,%9}, {%0,%1,%2,%3};"
        : "+f"(c[0]), "+f"(c[1]), "+f"(c[2]), "+f"(c[3])
        : "r"(a[0]), "r"(a[1]), "r"(a[2]), "r"(a[3]), "r"(b0), "r"(b1));
}
__device__ __forceinline__ void ldsm4(uint32_t* r, uint32_t addr) {
    asm volatile("ldmatrix.sync.aligned.m8n8.x4.shared.b16 {%0,%1,%2,%3}, [%4];"
        : "=r"(r[0]), "=r"(r[1]), "=r"(r[2]), "=r"(r[3]) : "r"(addr));
}

// layer 1 for one ray, 64 k (2 ksegs selected by ng), fp16 hi + unscaled lo
__device__ __forceinline__ void compute_h1(const float4* w1p, uint32_t* AhW, uint32_t* AlW,
                                           int ray, int ng,
                                           float px, float py, float pz)
{
    #pragma unroll
    for (int seg = 0; seg < 2; ++seg) {
        const float4* blk = w1p + (2 * ng + seg) * 34;
        #pragma unroll
        for (int j = 0; j < 4; ++j) {
            uint32_t hw[4], lw[4];
            #pragma unroll
            for (int q = 0; q < 4; ++q) {
                int kpl = j * 4 + q;
                float4 q0 = blk[kpl * 2], q1 = blk[kpl * 2 + 1];
                float h0 = fmaxf(fmaf(px, q0.x, fmaf(py, q0.y, fmaf(pz, q0.z, q0.w))), 0.f);
                float h1v = fmaxf(fmaf(px, q1.x, fmaf(py, q1.y, fmaf(pz, q1.z, q1.w))), 0.f);
                __half2 hh = __floats2half2_rn(h0, h1v);
                float2 bk = __half22float2(hh);
                __half2 ll = __floats2half2_rn(h0 - bk.x, h1v - bk.y);
                hw[q] = h2u(hh);
                lw[q] = h2u(ll);
            }
            int base = ray * ASTRIDE + (2 * ng + seg) * 16 + j * 4;
            *(uint4*)(AhW + base) = make_uint4(hw[0], hw[1], hw[2], hw[3]);
            *(uint4*)(AlW + base) = make_uint4(lw[0], lw[1], lw[2], lw[3]);
        }
    }
}

extern __shared__ float smem[];

__global__ void __launch_bounds__(NTHREADS, 1)
sphere_trace_kernel(const float* __restrict__ org,
                    const float* __restrict__ dir,
                    const float* __restrict__ W1, const float* __restrict__ b1,
                    const float* __restrict__ W2, const float* __restrict__ b2,
                    const float* __restrict__ W3, const float* __restrict__ b3,
                    const float* __restrict__ Wc1, const float* __restrict__ bc1,
                    const float* __restrict__ Wc2, const float* __restrict__ bc2,
                    float* __restrict__ out, int N)
{
    float4* Bpk = (float4*)(smem + OFF_BPK);
    float*  bw  = smem + OFF_BW;
    int*    stile = (int*)(smem + OFF_TILE);

    const uint32_t sb = smem_u32(smem);
    const int t      = threadIdx.x;
    const int lane   = t & 31;
    const int worker = t >> 6;          // 0..7 : independent 64-thread worker
    const int ng     = (t >> 5) & 1;    // warp-in-worker : outs [ng*64, ng*64+64)
    const int gid    = lane >> 2;
    const int tig    = lane & 3;
    const int barid  = 1 + worker;

    uint32_t* AhW = (uint32_t*)(smem + OFF_AH) + worker * AWORK;
    uint32_t* AlW = (uint32_t*)(smem + OFF_AL) + worker * AWORK;
    float*    scr = smem + OFF_SCR + worker * 256;  // part@0, color@64, asn@160
    float*    cp  = scr + 64;
    int*      asn = (int*)(scr + 160);

    // ---- one-time staging (whole CTA) ----
    for (int idx = t; idx < 4096; idx += NTHREADS) {
        int ln = idx & 31, jn = (idx >> 5) & 15, ks = idx >> 9;
        int n  = jn * 8 + (ln >> 2);
        int k0 = ks * 16 + 2 * (ln & 3);
        float w00 = W2[k0*HID + n],     w01 = W2[(k0+1)*HID + n];
        float w10 = W2[(k0+8)*HID + n], w11 = W2[(k0+9)*HID + n];
        __half2 bh0 = __floats2half2_rn(w00, w01);
        __half2 bh1 = __floats2half2_rn(w10, w11);
        float2 r0 = __half22float2(bh0), r1 = __half22float2(bh1);
        __half2 bl0 = __floats2half2_rn(w00 - r0.x, w01 - r0.y);
        __half2 bl1 = __floats2half2_rn(w10 - r1.x, w11 - r1.y);
        Bpk[idx] = make_float4(__uint_as_float(h2u(bh0)), __uint_as_float(h2u(bh1)),
                               __uint_as_float(h2u(bl0)), __uint_as_float(h2u(bl1)));
    }
    if (t < 128) {
        int kseg = t >> 5, klocal = t & 31, kpl = klocal >> 1, hh = klocal & 1;
        ((float4*)(smem + OFF_W1P))[kseg * 34 + kpl * 2 + hh] =
            make_float4(W1[t], W1[HID + t], W1[2*HID + t], b1[t]);
        float* wc1b = smem + OFF_WC1B;
        float* wc2b = smem + OFF_WC2B;
        wc1b[t*4+0] = Wc1[t];       wc1b[t*4+1] = Wc1[HID+t];
        wc1b[t*4+2] = Wc1[2*HID+t]; wc1b[t*4+3] = bc1[t];
        wc2b[t*4+0] = Wc2[3*t];     wc2b[t*4+1] = Wc2[3*t+1];
        wc2b[t*4+2] = Wc2[3*t+2];   wc2b[t*4+3] = 0.0f;
        bw[2*t]   = b2[t];
        bw[2*t+1] = W3[t];
    }
    if (t < 4) (smem + OFF_BC2)[t] = (t < 3) ? bc2[t] : 0.0f;
    const float bias3 = b3[0];
    __syncthreads();                  // only CTA-wide barrier

    const float4* w1p = (const float4*)(smem + OFF_W1P);

    const uint32_t ahAddr = sb + (OFF_AH + worker * AWORK) * 4
                          + (uint32_t)(lane & 15) * 272
                          + (uint32_t)((lane >> 4) & 1) * 16;
    const uint32_t alAddr = ahAddr + (OFF_AL - OFF_AH) * 4;
    const float4* bbase = Bpk + ng * 256 + lane;
    const float* bc = smem + OFF_BC2;

    // ---- initial ray grab: 32 rays per worker ----
    if ((t & 63) == 0) stile[worker] = atomicAdd(&g_tile_ctr, 32);
    BAR_W(barid);
    int myray = stile[worker] + lane;
    int mode = (myray < N) ? M_MARCH : M_INACT;

    float px = 0.f, py = 0.f, pz = 0.f, dx = 0.f, dy = 0.f, dz = 0.f;
    float dist = 0.f;
    bool hit = false;
    int it = 0;
    if (mode == M_MARCH) {
        px = org[3*myray]; py = org[3*myray+1]; pz = org[3*myray+2];
        dx = dir[3*myray]; dy = dir[3*myray+1]; dz = dir[3*myray+2];
        compute_h1(w1p, AhW, AlW, lane, ng, px, py, pz);
    }

    // ---- persistent per-lane march loop ----
    for (;;) {
        unsigned balM = __ballot_sync(0xffffffffu, mode == M_MARCH);
        unsigned balP = __ballot_sync(0xffffffffu, mode == M_PEND);
        if (!(balM | balP)) break;
        const bool doB = (balM != 0);
        const bool doR = (__popc(balP) >= RTHRESH) || !doB;

        if (doB) {
            BAR_W(barid);             // A writes visible

            // ===== phase B: single-accumulator 3-term fp16 mma, M32 x N64 =====
            {
                float c[2][8][4];
                #pragma unroll
                for (int mh = 0; mh < 2; ++mh)
                    #pragma unroll
                    for (int j = 0; j < 8; ++j)
                        #pragma unroll
                        for (int q = 0; q < 4; ++q) c[mh][j][q] = 0.f;

                #pragma unroll
                for (int ks = 0; ks < 8; ++ks) {
                    // hoisted operand loads: all B LDS.128 first, then ldsm
                    float4 bv[8];
                    #pragma unroll
                    for (int j = 0; j < 8; ++j) bv[j] = bbase[ks * 512 + j * 32];
                    uint32_t ah[2][4], al[2][4];
                    ldsm4(ah[0], ahAddr + ks * 32);
                    ldsm4(ah[1], ahAddr + 4352 + ks * 32);
                    ldsm4(al[0], alAddr + ks * 32);
                    ldsm4(al[1], alAddr + 4352 + ks * 32);
                    #pragma unroll
                    for (int j = 0; j < 8; ++j) {
                        uint32_t b0h = __float_as_uint(bv[j].x), b1h = __float_as_uint(bv[j].y);
                        uint32_t b0l = __float_as_uint(bv[j].z), b1l = __float_as_uint(bv[j].w);
                        mma16(c[0][j], ah[0], b0h, b1h);
                        mma16(c[1][j], ah[1], b0h, b1h);
                        mma16(c[0][j], al[0], b0h, b1h);
                        mma16(c[1][j], al[1], b0h, b1h);
                        mma16(c[0][j], ah[0], b0l, b1l);
                        mma16(c[1][j], ah[1], b0l, b1l);
                    }
                }

                float rs[2][2] = {{0.f, 0.f}, {0.f, 0.f}};
                #pragma unroll
                for (int mh = 0; mh < 2; ++mh) {
                    #pragma unroll
                    for (int j = 0; j < 8; ++j) {
                        const int n0 = ng * 64 + j * 8 + tig * 2;
                        float4 bwv = *(const float4*)(bw + n0 * 2);
                        float f0 = c[mh][j][0] + bwv.x;
                        float f1 = c[mh][j][1] + bwv.z;
                        float f2 = c[mh][j][2] + bwv.x;
                        float f3 = c[mh][j][3] + bwv.z;
                        rs[mh][0] = fmaf(fmaxf(f0, 0.f), bwv.y, rs[mh][0]);
                        rs[mh][0] = fmaf(fmaxf(f1, 0.f), bwv.w, rs[mh][0]);
                        rs[mh][1] = fmaf(fmaxf(f2, 0.f), bwv.y, rs[mh][1]);
                        rs[mh][1] = fmaf(fmaxf(f3, 0.f), bwv.w, rs[mh][1]);
                    }
                }
                #pragma unroll
                for (int off = 1; off < 4; off <<= 1) {
                    rs[0][0] += __shfl_xor_sync(0xffffffffu, rs[0][0], off);
                    rs[0][1] += __shfl_xor_sync(0xffffffffu, rs[0][1], off);
                    rs[1][0] += __shfl_xor_sync(0xffffffffu, rs[1][0], off);
                    rs[1][1] += __shfl_xor_sync(0xffffffffu, rs[1][1], off);
                }
                if (tig == 0) {
                    scr[(gid)      * 2 + ng] = rs[0][0];
                    scr[(gid + 8)  * 2 + ng] = rs[0][1];
                    scr[(gid + 16) * 2 + ng] = rs[1][0];
                    scr[(gid + 24) * 2 + ng] = rs[1][1];
                }
            }
            BAR_W(barid);             // part visible

            // ===== phase C: march (state mirrored identically in both warps) =====
            if (mode == M_MARCH) {
                float2 pp = *(const float2*)(scr + lane * 2);
                float sdf = bias3 + pp.x + pp.y;
                const bool valid = (sdf <= NEAR_T) && (dist < FAR_T);
                hit = hit || valid;
                if (valid) {
                    mode = M_PEND;
                } else {
                    dist += sdf;
                    px = fmaf(dx, sdf, px);
                    py = fmaf(dy, sdf, py);
                    pz = fmaf(dz, sdf, pz);
                    if (++it >= MAX_IT) mode = M_PEND;
                    else compute_h1(w1p, AhW, AlW, lane, ng, px, py, pz);
                }
            }
        }

        if (doR) {
            // color MLP: each warp computes its 64-j half for its lane's ray
            float c0 = 0.f, c1 = 0.f, c2 = 0.f;
            {
                const float4* wc1b = (const float4*)(smem + OFF_WC1B) + ng * 64;
                const float4* wc2b = (const float4*)(smem + OFF_WC2B) + ng * 64;
                #pragma unroll 4
                for (int j = 0; j < 64; ++j) {
                    float4 q  = wc1b[j];
                    float4 wv = wc2b[j];
                    float h = fmaf(px, q.x, fmaf(py, q.y, fmaf(pz, q.z, q.w)));
                    h = fmaxf(h, 0.0f);
                    c0 = fmaf(h, wv.x, c0);
                    c1 = fmaf(h, wv.y, c1);
                    c2 = fmaf(h, wv.z, c2);
                }
            }
            if (ng == 1) {
                cp[lane * 3 + 0] = c0;
                cp[lane * 3 + 1] = c1;
                cp[lane * 3 + 2] = c2;
            }
            unsigned balP2 = __ballot_sync(0xffffffffu, mode == M_PEND);
            if (ng == 0) {
                int cnt = __popc(balP2);
                int base = 0;
                if (lane == 0 && cnt) base = atomicAdd(&g_tile_ctr, cnt);
                base = __shfl_sync(0xffffffffu, base, 0);
                if (mode == M_PEND)
                    asn[lane] = base + __popc(balP2 & ((1u << lane) - 1u));
            }
            BAR_W(barid);             // cp + asn visible
            if (mode == M_PEND) {
                if (ng == 0) {
                    const bool mask = hit || (dist < FAR_T);
                    float o0 = c0 + cp[lane * 3 + 0] + bc[0];
                    float o1 = c1 + cp[lane * 3 + 1] + bc[1];
                    float o2 = c2 + cp[lane * 3 + 2] + bc[2];
                    out[3*myray]     = mask ? (1.0f / (1.0f + expf(-o0))) : 0.0f;
                    out[3*myray + 1] = mask ? (1.0f / (1.0f + expf(-o1))) : 0.0f;
                    out[3*myray + 2] = mask ? (1.0f / (1.0f + expf(-o2))) : 0.0f;
                }
                int nr = asn[lane];
                if (nr < N) {
                    myray = nr;
                    px = org[3*nr]; py = org[3*nr+1]; pz = org[3*nr+2];
                    dx = dir[3*nr]; dy = dir[3*nr+1]; dz = dir[3*nr+2];
                    dist = 0.f; hit = false; it = 0;
                    mode = M_MARCH;
                    compute_h1(w1p, AhW, AlW, lane, ng, px, py, pz);
                } else {
                    mode = M_INACT;
                }
            }
        }
    }
}

extern "C" void kernel_launch(void* const* d_in, const int* in_sizes, int n_in,
                              void* d_out, int out_size)
{
    const float* org = (const float*)d_in[0];
    const float* dir = (const float*)d_in[1];
    const float* W1  = (const float*)d_in[2];
    const float* b1  = (const float*)d_in[3];
    const float* W2  = (const float*)d_in[4];
    const float* b2  = (const float*)d_in[5];
    const float* W3  = (const float*)d_in[6];
    const float* b3  = (const float*)d_in[7];
    const float* Wc1 = (const float*)d_in[8];
    const float* bc1 = (const float*)d_in[9];
    const float* Wc2 = (const float*)d_in[10];
    const float* bc2 = (const float*)d_in[11];
    float* out = (float*)d_out;

    const int N = in_sizes[0] / 3;
    const int smem_bytes = SMEM_WORDS * sizeof(float);

    cudaFuncSetAttribute(sphere_trace_kernel,
                         cudaFuncAttributeMaxDynamicSharedMemorySize, smem_bytes);

    reset_ctr_kernel<<<1, 1>>>();

    int nblocks = 152;                 // 1 persistent CTA/SM, 8 workers of 64 threads
    sphere_trace_kernel<<<nblocks, NTHREADS, smem_bytes>>>(
        org, dir, W1, b1, W2, b2, W3, b3, Wc1, bc1, Wc2, bc2, out, N);
}